// round 8
// baseline (speedup 1.0000x reference)
#include <cuda_runtime.h>
#include <cuda_bf16.h>

// ---------------------------------------------------------------------------
// ZBL screened-Coulomb pair energy with switching polynomial, scatter to atoms
//
// Inputs (metadata order):
//   0: rij             float32 [E]
//   1: covalent_radii  float32 [4]
//   2: atomic_numbers  float32 [4]
//   3: first_atom      int32   [E]
//   4: second_atom     int32   [E]
//   5: atom_type_index int32   [N]
// Output: float32 [N]
// ---------------------------------------------------------------------------

#define MAX_PACK_WORDS 16384   // up to 262144 atoms at 2 bits/atom

__device__ unsigned int g_packed[MAX_PACK_WORDS];

// ---- fused: zero output + pack atom types to 2 bits/atom ------------------
__global__ void zbl_setup(const int* __restrict__ type,
                          float* __restrict__ out, int n_atoms) {
    int i = blockIdx.x * blockDim.x + threadIdx.x;
    if (i < n_atoms) out[i] = 0.0f;
    int nw = (n_atoms + 15) >> 4;
    if (i < nw) {
        unsigned v = 0;
        int base = i << 4;
        int lim  = n_atoms - base;
        if (lim > 16) lim = 16;
        for (int k = 0; k < lim; k++)
            v |= ((unsigned)type[base + k] & 3u) << (2 * k);
        g_packed[i] = v;
    }
}

// ---- per-edge math --------------------------------------------------------
// tabA[p] = (rc, inv_a, halfFactor, A/6)   tabB[p] = (B/8, C/2)
__device__ __forceinline__ void zbl_edge(float r, int i,
                                         unsigned wi, unsigned wj, int j,
                                         const float4* __restrict__ tabA,
                                         const float2* __restrict__ tabB,
                                         float* __restrict__ out) {
    int ti = (wi >> ((i & 15) * 2)) & 3;
    int tj = (wj >> ((j & 15) * 2)) & 3;
    int p  = (ti << 2) | tj;
    float4 a4 = tabA[p];
    if (r <= a4.x) {
        float2 b2 = tabB[p];
        float x = -r * a4.y;          // -r / a
        // d_k * log2(e): exp2f maps straight to MUFU.EX2
        float s = 0.02817f * exp2f(0.29088274f * x)
                + 0.28022f * exp2f(0.58126184f * x)
                + 0.50986f * exp2f(1.35944400f * x)
                + 0.18175f * exp2f(4.61651600f * x);
        float r3  = r * r * r;
        float val = a4.z * __fdividef(s, r) + r3 * (a4.w + b2.x * r) + b2.y;
        atomicAdd(out + i, val);
    }
}

__global__ __launch_bounds__(1024, 2)
void zbl_edge_kernel(const float* __restrict__ rij,
                     const int*   __restrict__ fa,
                     const int*   __restrict__ sa,
                     const float* __restrict__ cr,
                     const float* __restrict__ Z,
                     float*       __restrict__ out,
                     int E, int n_atoms) {
    // dynamic smem: [0..16) float4 tabA | [16..24) float2-as-float4 pad | pack
    extern __shared__ unsigned shraw[];
    float4*   tabA    = (float4*)shraw;            // 16 entries = 256 B
    float2*   tabB    = (float2*)(shraw + 64);     // 16 entries = 128 B
    unsigned* sh_pack = shraw + 96;                // nw words

    if (threadIdx.x < 16) {
        int p = threadIdx.x;
        int ti = p >> 2, tj = p & 3;
        const float c[4] = {0.02817f, 0.28022f, 0.50986f, 0.18175f};
        const float d[4] = {0.20162f, 0.4029f, 0.94229f, 3.1998f};
        float zi = Z[ti], zj = Z[tj];
        float a     = 0.4685f / (powf(zi, 0.23f) + powf(zj, 0.23f));
        float inv_a = 1.0f / a;
        float rc    = cr[ti] + cr[tj];
        float phi = 0.f, dphi = 0.f, d2phi = 0.f;
#pragma unroll
        for (int k = 0; k < 4; k++) {
            float da = d[k] * inv_a;
            float ex = expf(-rc * da);
            phi   += c[k] * ex;
            dphi  -= c[k] * da * ex;
            d2phi += c[k] * da * da * ex;
        }
        float factor = 14.399645478425668f * zi * zj;
        float irc  = 1.0f / rc;
        float ec   = factor * irc * phi;
        float dec  = factor * irc * (-phi * irc + dphi);
        float d2ec = factor * irc * (d2phi - 2.0f * irc * dphi
                                     + 2.0f * phi * irc * irc);
        float A = (-3.0f * dec + rc * d2ec) * irc * irc;
        float B = ( 2.0f * dec - rc * d2ec) * irc * irc * irc;
        float C = -ec + rc * dec * 0.5f - rc * rc * d2ec * (1.0f / 12.0f);
        tabA[p] = make_float4(rc, inv_a, 0.5f * factor, A * (1.0f / 6.0f));
        tabB[p] = make_float2(B * 0.125f, C * 0.5f);
    }

    // copy the 2-bit type pack into SMEM (coalesced, ~12.5K words)
    int nw = (n_atoms + 15) >> 4;
    for (int k = threadIdx.x; k < nw; k += blockDim.x)
        sh_pack[k] = g_packed[k];
    __syncthreads();

    int nvec = E >> 2;
    const float4* r4p = (const float4*)rij;
    const int4*   f4p = (const int4*)fa;
    const int4*   s4p = (const int4*)sa;

    for (int v = blockIdx.x * blockDim.x + threadIdx.x; v < nvec;
         v += gridDim.x * blockDim.x) {
        float4 r4 = __ldcs(r4p + v);
        int4   f4 = __ldcs(f4p + v);
        int4   s4 = __ldcs(s4p + v);

        // SMEM-crossbar gathers: random LDS costs ~conflict-degree phases,
        // not ~30 L1tex wavefronts like a random LDG.
        unsigned wf0 = sh_pack[f4.x >> 4];
        unsigned wf1 = sh_pack[f4.y >> 4];
        unsigned wf2 = sh_pack[f4.z >> 4];
        unsigned wf3 = sh_pack[f4.w >> 4];
        unsigned ws0 = sh_pack[s4.x >> 4];
        unsigned ws1 = sh_pack[s4.y >> 4];
        unsigned ws2 = sh_pack[s4.z >> 4];
        unsigned ws3 = sh_pack[s4.w >> 4];

        zbl_edge(r4.x, f4.x, wf0, ws0, s4.x, tabA, tabB, out);
        zbl_edge(r4.y, f4.y, wf1, ws1, s4.y, tabA, tabB, out);
        zbl_edge(r4.z, f4.z, wf2, ws2, s4.z, tabA, tabB, out);
        zbl_edge(r4.w, f4.w, wf3, ws3, s4.w, tabA, tabB, out);
    }

    int tail = E & 3;
    if (blockIdx.x == 0 && (int)threadIdx.x < tail) {
        int e = (nvec << 2) + threadIdx.x;
        int i = fa[e], j = sa[e];
        zbl_edge(rij[e], i, sh_pack[i >> 4], sh_pack[j >> 4], j,
                 tabA, tabB, out);
    }
}

// ---------------------------------------------------------------------------
extern "C" void kernel_launch(void* const* d_in, const int* in_sizes, int n_in,
                              void* d_out, int out_size) {
    const float* rij = (const float*)d_in[0];
    const float* cr  = (const float*)d_in[1];
    const float* Z   = (const float*)d_in[2];
    const int*   fa  = (const int*)d_in[3];
    const int*   sa  = (const int*)d_in[4];
    const int*   ty  = (const int*)d_in[5];
    int E       = in_sizes[0];
    int n_atoms = out_size;
    float* out  = (float*)d_out;

    zbl_setup<<<(n_atoms + 1023) / 1024, 1024>>>(ty, out, n_atoms);

    int nw = (n_atoms + 15) >> 4;
    size_t shbytes = 96 * sizeof(unsigned) + (size_t)nw * sizeof(unsigned);
    cudaFuncSetAttribute(zbl_edge_kernel,
                         cudaFuncAttributeMaxDynamicSharedMemorySize,
                         (int)((shbytes + 1023) & ~1023ull));
    zbl_edge_kernel<<<296, 1024, shbytes>>>(rij, fa, sa, cr, Z, out,
                                            E, n_atoms);
}